// round 15
// baseline (speedup 1.0000x reference)
#include <cuda_runtime.h>
#include <cuda_fp16.h>
#include <cstdint>

#define T_STEPS 512
#define B_SZ 64
#define D_SZ 1024
#define H_SZ 1024
#define G4 4096
#define M_TOT (T_STEPS * B_SZ)   // 32768
#define NBLK 128

// ---------------- device scratch (static, allocation-free) ----------------
__device__ __align__(128) __half   g_Xh[(size_t)M_TOT * D_SZ];   // 64 MB
__device__ __align__(128) __half   g_Wxh[D_SZ * G4];             // 8 MB [col][k]
__device__ __align__(128) __half   g_Whp[H_SZ * G4];             // 8 MB [col][k]
__device__ __align__(128) float    g_b4[G4];
__device__ __align__(128) __half   g_Gxh[(size_t)M_TOT * G4];    // 256 MB
// h double-buffered; each buffer = 4 k-quarters x (64 rows x 256 halfs);
// quarter rows are 512 B; 16 B chunks XOR-swizzled by (row&7) within each
// 128 B group -> bulk-copied SMEM image is ldmatrix-conflict-free.
__device__ __align__(128) __half   g_h[2][65536];
// four monotonic barrier counters (one per producer k-quarter), 128 B apart
__device__ __align__(128) unsigned g_bar2[128];

// ---------------- helpers ----------------
__device__ __forceinline__ void mma_f16(float* c, const uint32_t* a, const uint32_t* b) {
    asm volatile(
        "mma.sync.aligned.m16n8k16.row.col.f32.f16.f16.f32 "
        "{%0,%1,%2,%3}, {%4,%5,%6,%7}, {%8,%9}, {%0,%1,%2,%3};"
        : "+f"(c[0]), "+f"(c[1]), "+f"(c[2]), "+f"(c[3])
        : "r"(a[0]), "r"(a[1]), "r"(a[2]), "r"(a[3]), "r"(b[0]), "r"(b[1]));
}

__device__ __forceinline__ void ldsm_x4(uint32_t& r0, uint32_t& r1, uint32_t& r2,
                                        uint32_t& r3, uint32_t addr) {
    asm volatile("ldmatrix.sync.aligned.m8n8.x4.shared.b16 {%0,%1,%2,%3}, [%4];"
                 : "=r"(r0), "=r"(r1), "=r"(r2), "=r"(r3) : "r"(addr));
}

__device__ __forceinline__ void cp_async16(uint32_t smem_addr, const void* gptr) {
    asm volatile("cp.async.cg.shared.global [%0], [%1], 16;"
                 :: "r"(smem_addr), "l"(gptr));
}
#define CP_COMMIT() asm volatile("cp.async.commit_group;")
#define CP_WAIT(N)  asm volatile("cp.async.wait_group %0;" :: "n"(N))

#define MBAR_INIT(addr, cnt) \
    asm volatile("mbarrier.init.shared.b64 [%0], %1;" :: "r"(addr), "r"(cnt) : "memory")
#define MBAR_EXPECT_TX(addr, tx) \
    asm volatile("mbarrier.arrive.expect_tx.shared.b64 _, [%0], %1;" \
                 :: "r"(addr), "r"(tx) : "memory")

__device__ __forceinline__ void mbar_wait_parity(uint32_t mbar, uint32_t parity) {
    asm volatile(
        "{\n\t.reg .pred P;\n\t"
        "WL_%=:\n\t"
        "mbarrier.try_wait.parity.acquire.cta.shared::cta.b64 P, [%0], %1, 0x989680;\n\t"
        "@P bra.uni WD_%=;\n\t"
        "bra.uni WL_%=;\n\t"
        "WD_%=:\n\t}"
        :: "r"(mbar), "r"(parity) : "memory");
}

// 1D bulk copy global -> local SMEM, completion via local mbarrier (R10-proven)
__device__ __forceinline__ void bulk_g2s(uint32_t dst, const void* src, uint32_t bytes,
                                         uint32_t mbar) {
    asm volatile(
        "cp.async.bulk.shared::cluster.global.mbarrier::complete_tx::bytes"
        " [%0], [%1], %2, [%3];"
        :: "r"(dst), "l"(src), "r"(bytes), "r"(mbar) : "memory");
}

__device__ __forceinline__ float sigmoid_fast(float x) {
    return __fdividef(1.0f, 1.0f + __expf(-x));
}
__device__ __forceinline__ float tanh_fast(float x) {
    float e = __expf(-2.0f * x);
    return __fdividef(1.0f - e, 1.0f + e);
}

// ---------------- kernel 0: repack weights/bias, convert X, init state ------
__global__ void pack_kernel(const float* __restrict__ X,
                            const float* __restrict__ Wf, const float* __restrict__ Wi,
                            const float* __restrict__ Wg, const float* __restrict__ Wo,
                            const float* __restrict__ bf, const float* __restrict__ bi,
                            const float* __restrict__ bg, const float* __restrict__ bo) {
    int idx = blockIdx.x * blockDim.x + threadIdx.x;   // over 4M
    if (idx < D_SZ * G4) {
        int j = idx >> 10;       // packed col
        int k = idx & 1023;
        int n = j >> 2;
        int g = j & 3;
        const float* W = (g == 0) ? Wf : (g == 1) ? Wi : (g == 2) ? Wg : Wo;
        g_Wxh[idx] = __float2half(W[k * H_SZ + n]);
        g_Whp[idx] = __float2half(W[(D_SZ + k) * H_SZ + n]);
    }
    // X -> fp16: 8M float4 handled 2 per thread
    #pragma unroll
    for (int r = 0; r < 2; r++) {
        size_t i = (size_t)idx + (size_t)r * ((size_t)D_SZ * G4);
        float4 v = ((const float4*)X)[i];
        __half2* dst = (__half2*)g_Xh;
        dst[2 * i]     = __floats2half2_rn(v.x, v.y);
        dst[2 * i + 1] = __floats2half2_rn(v.z, v.w);
    }
    if (idx < G4) {
        int n = idx >> 2, g = idx & 3;
        const float* bb = (g == 0) ? bf : (g == 1) ? bi : (g == 2) ? bg : bo;
        g_b4[idx] = bb[n];
    }
    if (idx < 65536) g_h[0][idx] = __float2half(0.0f);
    if (idx < 128) g_bar2[idx] = 0u;
}

// ---------------- kernel 1: Gx = X @ Wx + b (3-stage cp.async + ldmatrix) ---
#define GX_STAGE_B 32768
#define GX_SMEM    (3 * GX_STAGE_B)

__global__ __launch_bounds__(256, 2) void gemm_x_kernel() {
    extern __shared__ unsigned char dsm[];
    uint32_t sbase = (uint32_t)__cvta_generic_to_shared(dsm);

    int tid  = threadIdx.x;
    int warp = tid >> 5, lane = tid & 31;
    int wm = warp >> 2, wn = warp & 3;
    int grp = lane >> 2, tig = lane & 3;
    int g8  = lane >> 3, lr = lane & 7;
    int bm = blockIdx.y * 128, bn = blockIdx.x * 128;

    int cr[4], cc[4];
    uint32_t soff[4];
    #pragma unroll
    for (int i = 0; i < 4; i++) {
        int l = tid + i * 256;
        cr[i] = l >> 3;
        cc[i] = l & 7;
        soff[i] = (uint32_t)(cr[i] * 128 + ((cc[i] ^ (cr[i] & 7)) * 16));
    }

    auto issue = [&](int stage, int kt) {
        uint32_t st = sbase + stage * GX_STAGE_B;
        #pragma unroll
        for (int i = 0; i < 4; i++) {
            cp_async16(st + soff[i],
                       &g_Xh[(size_t)(bm + cr[i]) * D_SZ + kt * 64 + cc[i] * 8]);
            cp_async16(st + 16384 + soff[i],
                       &g_Wxh[(size_t)(bn + cr[i]) * D_SZ + kt * 64 + cc[i] * 8]);
        }
        CP_COMMIT();
    };

    float acc[4][4][4];
    #pragma unroll
    for (int i = 0; i < 4; i++)
        #pragma unroll
        for (int j = 0; j < 4; j++)
            #pragma unroll
            for (int k = 0; k < 4; k++) acc[i][j][k] = 0.0f;

    issue(0, 0);
    issue(1, 1);

    for (int it = 0; it < 16; it++) {
        if (it < 15) { CP_WAIT(1); } else { CP_WAIT(0); }
        __syncthreads();
        if (it + 2 < 16) issue((it + 2) % 3, it + 2);

        uint32_t st = sbase + (it % 3) * GX_STAGE_B;
        #pragma unroll
        for (int k16 = 0; k16 < 4; k16++) {
            uint32_t A[4][4], Bf[2][4];
            #pragma unroll
            for (int mt = 0; mt < 4; mt++) {
                int m = wm * 64 + mt * 16 + (g8 & 1) * 8 + lr;
                int ch = k16 * 2 + (g8 >> 1);
                ldsm_x4(A[mt][0], A[mt][1], A[mt][2], A[mt][3],
                        st + m * 128 + ((ch ^ (m & 7)) * 16));
            }
            #pragma unroll
            for (int p = 0; p < 2; p++) {
                int n = wn * 32 + p * 16 + (g8 >> 1) * 8 + lr;
                int ch = k16 * 2 + (g8 & 1);
                ldsm_x4(Bf[p][0], Bf[p][1], Bf[p][2], Bf[p][3],
                        st + 16384 + n * 128 + ((ch ^ (n & 7)) * 16));
            }
            #pragma unroll
            for (int mt = 0; mt < 4; mt++)
                #pragma unroll
                for (int p = 0; p < 2; p++) {
                    mma_f16(acc[mt][2 * p],     A[mt], &Bf[p][0]);
                    mma_f16(acc[mt][2 * p + 1], A[mt], &Bf[p][2]);
                }
        }
        __syncthreads();
    }

    __half* sE = (__half*)dsm;     // 128 x 136 halfs
    #pragma unroll
    for (int mt = 0; mt < 4; mt++)
        #pragma unroll
        for (int nt = 0; nt < 4; nt++) {
            int lc = wn * 32 + nt * 8 + 2 * tig;
            int col = bn + lc;
            float b0 = g_b4[col], b1 = g_b4[col + 1];
            int r = wm * 64 + mt * 16 + grp;
            *(__half2*)&sE[r * 136 + lc] =
                __floats2half2_rn(acc[mt][nt][0] + b0, acc[mt][nt][1] + b1);
            *(__half2*)&sE[(r + 8) * 136 + lc] =
                __floats2half2_rn(acc[mt][nt][2] + b0, acc[mt][nt][3] + b1);
        }
    __syncthreads();
    #pragma unroll
    for (int i = 0; i < 8; i++) {
        int l = tid + i * 256;
        int row = l >> 4, c8 = l & 15;
        *(uint4*)&g_Gxh[(size_t)(bm + row) * G4 + bn + c8 * 8] =
            *(const uint4*)&sE[row * 136 + c8 * 8];
    }
}

// ---------------- kernel 2: persistent recurrence ---------------------------
// R14 base, producer/consumer pipeline refined from halves to k-QUARTERS:
//  - h stored as 4 quarters (64 rows x 512 B) per buffer
//  - 4 producer counters (quarter = blk>>5, 32 CTAs each)
//  - tid0: poll q -> issue 32 KB TMA -> next q
//  - warps wait only their own quarter's mbarrier (wk0/1: q0,q2; wk2/3: q1,q3)
#define SW_STRIDE 1032                 // halfs
#define OFF_HQ   66048                 // 4 quarters x 32768 B
#define OFF_GA   197120
#define OFF_GB   205568
#define OFF_MBAR 214016                // 4 mbarriers
#define SMEM_TOTAL_R 214048
#define QBYTES   32768

__global__ __launch_bounds__(256, 1) void lstm_persistent_kernel(
        float* __restrict__ out, int write_tails) {
    extern __shared__ unsigned char smem[];
    __half* sW = (__half*)smem;
    float (*sGA)[33] = (float(*)[33])(smem + OFF_GA);
    float (*sGB)[33] = (float(*)[33])(smem + OFF_GB);
    uint32_t sb = (uint32_t)__cvta_generic_to_shared(smem);

    int tid  = threadIdx.x;
    int warp = tid >> 5, lane = tid & 31;
    int wk = warp >> 1, wm = warp & 1;     // 4 k-split x 2 m-split
    int grp = lane >> 2, tig = lane & 3;
    int g8 = lane >> 3, lr = lane & 7;
    int blk = blockIdx.x;

    // one-time: Wh slice ([col][k] fp16) -> padded SMEM
    {
        const uint4* src = (const uint4*)(g_Whp + (size_t)blk * 32768);
        #pragma unroll
        for (int i = 0; i < 16; i++) {
            int l = tid + i * 256;
            int c = l >> 7, w = l & 127;
            *(uint4*)(sW + c * SW_STRIDE + w * 8) = src[l];
        }
    }
    if (tid == 0) {
        #pragma unroll
        for (int q = 0; q < 4; q++) MBAR_INIT(sb + OFF_MBAR + q * 8, 1);
    }
    __syncthreads();

    // per-lane ldmatrix A row (constant across steps)
    int rowA = wm * 32 + (g8 & 1) * 8 + lr;

    // per-thread pointwise coordinates
    int pr = (tid * 2) >> 3;          // batch row 0..63
    int pc = (tid * 2) & 7;           // local h-col (even)
    int pn = blk * 8 + pc;            // global h-col (even)
    int qp   = pn >> 8;               // producer k-quarter
    int hch  = (pn & 255) >> 3;       // 16 B chunk within 512 B row
    int qcnt = (blk >> 5) * 32;       // counter slot for this CTA's quarter

    float creg[2] = {0.0f, 0.0f};

    // Gx prefetch for t=0
    uint2 gxr[2];
    #pragma unroll
    for (int p = 0; p < 2; p++) {
        gxr[p] = __ldcg((const uint2*)&g_Gxh[(size_t)pr * G4 + blk * 32 +
                                             (pc + p) * 4]);
    }

    // step-0 h loads (initial h ready; no barrier needed)
    if (tid == 0) {
        const char* hbg = (const char*)g_h;
        #pragma unroll
        for (int q = 0; q < 4; q++) {
            uint32_t mb = sb + OFF_MBAR + q * 8;
            MBAR_EXPECT_TX(mb, QBYTES);
            bulk_g2s(sb + OFF_HQ + q * QBYTES, hbg + q * QBYTES, QBYTES, mb);
        }
    }

    for (int t = 0; t < T_STEPS; t++) {
        float acc[2][4][4];
        #pragma unroll
        for (int i = 0; i < 2; i++)
            #pragma unroll
            for (int j = 0; j < 4; j++)
                #pragma unroll
                for (int k = 0; k < 4; k++) acc[i][j][k] = 0.0f;

        #pragma unroll
        for (int part = 0; part < 2; part++) {
            int q = part * 2 + (wk >> 1);
            mbar_wait_parity(sb + OFF_MBAR + q * 8, (uint32_t)(t & 1));
            uint32_t qb = sb + OFF_HQ + q * QBYTES;
            #pragma unroll
            for (int kk = 0; kk < 8; kk++) {
                int lk = (wk & 1) * 8 + kk;       // local k16 in quarter
                int c  = lk * 2 + (g8 >> 1);      // chunk 0..31
                uint32_t A0[4], A1[4];
                {
                    int row = rowA;
                    uint32_t a = qb + row * 512 +
                                 (uint32_t)((((c & 7) ^ (row & 7)) | (c & ~7)) * 16);
                    ldsm_x4(A0[0], A0[1], A0[2], A0[3], a);
                    row = rowA + 16;
                    a = qb + row * 512 +
                        (uint32_t)((((c & 7) ^ (row & 7)) | (c & ~7)) * 16);
                    ldsm_x4(A1[0], A1[1], A1[2], A1[3], a);
                }
                int kg = (q * 16 + lk) * 16 + 2 * tig;
                #pragma unroll
                for (int nt = 0; nt < 4; nt++) {
                    const __half* pb = sW + (nt * 8 + grp) * SW_STRIDE + kg;
                    uint32_t B[2] = { *(const uint32_t*)pb,
                                      *(const uint32_t*)(pb + 8) };
                    mma_f16(acc[0][nt], A0, B);
                    mma_f16(acc[1][nt], A1, B);
                }
            }
        }

        // 2-round k-split reduction
        if ((wk & 1) == 0) {
            float (*d)[33] = (wk == 0) ? sGA : sGB;
            #pragma unroll
            for (int mt = 0; mt < 2; mt++)
                #pragma unroll
                for (int nt = 0; nt < 4; nt++) {
                    int r = wm * 32 + mt * 16 + grp, c = nt * 8 + 2 * tig;
                    d[r    ][c]     = acc[mt][nt][0];
                    d[r    ][c + 1] = acc[mt][nt][1];
                    d[r + 8][c]     = acc[mt][nt][2];
                    d[r + 8][c + 1] = acc[mt][nt][3];
                }
        }
        __syncthreads();
        if ((wk & 1) == 1) {
            float (*d)[33] = (wk == 1) ? sGA : sGB;
            #pragma unroll
            for (int mt = 0; mt < 2; mt++)
                #pragma unroll
                for (int nt = 0; nt < 4; nt++) {
                    int r = wm * 32 + mt * 16 + grp, c = nt * 8 + 2 * tig;
                    d[r    ][c]     += acc[mt][nt][0];
                    d[r    ][c + 1] += acc[mt][nt][1];
                    d[r + 8][c]     += acc[mt][nt][2];
                    d[r + 8][c + 1] += acc[mt][nt][3];
                }
        }
        __syncthreads();

        // fused pointwise: compute, store ONLY h, fence, early arrive
        float hn2[2], cn2[2];
        #pragma unroll
        for (int p = 0; p < 2; p++) {
            int c = pc + p;
            float2 g01 = __half22float2(*(__half2*)&gxr[p].x);
            float2 g23 = __half22float2(*(__half2*)&gxr[p].y);
            float pf = sGA[pr][c * 4 + 0] + sGB[pr][c * 4 + 0] + g01.x;
            float pi = sGA[pr][c * 4 + 1] + sGB[pr][c * 4 + 1] + g01.y;
            float pg = sGA[pr][c * 4 + 2] + sGB[pr][c * 4 + 2] + g23.x;
            float po = sGA[pr][c * 4 + 3] + sGB[pr][c * 4 + 3] + g23.y;
            float f = sigmoid_fast(pf);
            float i = sigmoid_fast(pi);
            float g = tanh_fast(pg);
            float o = sigmoid_fast(po);
            float cn = f * creg[p] + i * g;
            creg[p] = cn;
            cn2[p] = cn;
            hn2[p] = o * tanh_fast(cn);
        }
        // packed h store into the swizzled quarter image
        {
            char* hout = (char*)g_h + (size_t)((t + 1) & 1) * 131072 +
                         (size_t)qp * QBYTES;
            uint32_t off = (uint32_t)pr * 512 +
                           (uint32_t)((((hch & 7) ^ (pr & 7)) | (hch & ~7)) * 16) +
                           (uint32_t)(pn & 7) * 2;
            *(__half2*)(hout + off) = __floats2half2_rn(hn2[0], hn2[1]);
        }
        __threadfence();
        __syncthreads();
        // EARLY arrival on this CTA's quarter counter
        if (t < T_STEPS - 1 && tid == 0)
            atomicAdd(&g_bar2[qcnt], 1u);

        // out[] stores + tails + Gx(t+1) prefetch overlap the barrier wait
        *(float2*)&out[(size_t)(t * B_SZ + pr) * H_SZ + pn] =
            make_float2(hn2[0], hn2[1]);
        if (t == T_STEPS - 1 && write_tails) {
            int ci = pr * H_SZ + pn;
            *(float2*)&out[(size_t)T_STEPS * B_SZ * H_SZ + ci] =
                make_float2(hn2[0], hn2[1]);
            *(float2*)&out[(size_t)T_STEPS * B_SZ * H_SZ + B_SZ * H_SZ + ci] =
                make_float2(cn2[0], cn2[1]);
        }
        {
            int tn = (t + 1 < T_STEPS) ? t + 1 : t;
            #pragma unroll
            for (int p = 0; p < 2; p++) {
                gxr[p] = __ldcg((const uint2*)&g_Gxh[(size_t)(tn * B_SZ + pr) * G4 +
                                                     blk * 32 + (pc + p) * 4]);
            }
        }

        // tid0: per-quarter poll -> issue 32 KB TMA; no release syncthreads.
        if (t < T_STEPS - 1 && tid == 0) {
            unsigned target = (unsigned)(t + 1) * 32u;
            const char* hbg = (const char*)g_h + (size_t)((t + 1) & 1) * 131072;
            #pragma unroll
            for (int q = 0; q < 4; q++) {
                while (*((volatile unsigned*)&g_bar2[q * 32]) < target) {
                    __nanosleep(20);
                }
                uint32_t mb = sb + OFF_MBAR + q * 8;
                MBAR_EXPECT_TX(mb, QBYTES);
                bulk_g2s(sb + OFF_HQ + q * QBYTES, hbg + q * QBYTES, QBYTES, mb);
            }
        }
    }
}

// ---------------- launch ----------------
extern "C" void kernel_launch(void* const* d_in, const int* in_sizes, int n_in,
                              void* d_out, int out_size) {
    const float* x  = (const float*)d_in[0];
    const float* Wf = (const float*)d_in[1];
    const float* bf = (const float*)d_in[2];
    const float* Wi = (const float*)d_in[3];
    const float* bi = (const float*)d_in[4];
    const float* Wg = (const float*)d_in[5];
    const float* bg = (const float*)d_in[6];
    const float* Wo = (const float*)d_in[7];
    const float* bo = (const float*)d_in[8];
    float* out = (float*)d_out;

    int write_tails =
        (out_size >= T_STEPS * B_SZ * H_SZ + 2 * B_SZ * H_SZ) ? 1 : 0;

    static int smem_set = 0;
    if (!smem_set) {
        cudaFuncSetAttribute(lstm_persistent_kernel,
                             cudaFuncAttributeMaxDynamicSharedMemorySize,
                             SMEM_TOTAL_R);
        cudaFuncSetAttribute(gemm_x_kernel,
                             cudaFuncAttributeMaxDynamicSharedMemorySize,
                             GX_SMEM);
        smem_set = 1;
    }

    pack_kernel<<<(D_SZ * G4 + 255) / 256, 256>>>(x, Wf, Wi, Wg, Wo,
                                                  bf, bi, bg, bo);

    dim3 g1(G4 / 128, M_TOT / 128);
    gemm_x_kernel<<<g1, 256, GX_SMEM>>>();

    lstm_persistent_kernel<<<NBLK, 256, SMEM_TOTAL_R>>>(out, write_tails);
}

// round 16
// speedup vs baseline: 1.0304x; 1.0304x over previous
#include <cuda_runtime.h>
#include <cuda_fp16.h>
#include <cstdint>

#define T_STEPS 512
#define B_SZ 64
#define D_SZ 1024
#define H_SZ 1024
#define G4 4096
#define M_TOT (T_STEPS * B_SZ)   // 32768
#define NBLK 128

// ---------------- device scratch (static, allocation-free) ----------------
__device__ __align__(128) __half   g_Xh[(size_t)M_TOT * D_SZ];   // 64 MB
__device__ __align__(128) __half   g_Wxh[D_SZ * G4];             // 8 MB [col][k]
__device__ __align__(128) __half   g_Whp[H_SZ * G4];             // 8 MB [col][k]
__device__ __align__(128) float    g_b4[G4];
__device__ __align__(128) __half   g_Gxh[(size_t)M_TOT * G4];    // 256 MB
// h double-buffered; each buffer = 4 k-quarters x (64 rows x 256 halfs);
// quarter rows are 512 B; 16 B chunks XOR-swizzled by (row&7) within each
// 128 B group -> bulk-copied SMEM image is ldmatrix-conflict-free.
__device__ __align__(128) __half   g_h[2][65536];
// four monotonic barrier counters (one per producer k-quarter), 128 B apart
__device__ __align__(128) unsigned g_bar2[128];

// ---------------- helpers ----------------
__device__ __forceinline__ void mma_f16(float* c, const uint32_t* a, const uint32_t* b) {
    asm volatile(
        "mma.sync.aligned.m16n8k16.row.col.f32.f16.f16.f32 "
        "{%0,%1,%2,%3}, {%4,%5,%6,%7}, {%8,%9}, {%0,%1,%2,%3};"
        : "+f"(c[0]), "+f"(c[1]), "+f"(c[2]), "+f"(c[3])
        : "r"(a[0]), "r"(a[1]), "r"(a[2]), "r"(a[3]), "r"(b[0]), "r"(b[1]));
}

__device__ __forceinline__ void ldsm_x4(uint32_t& r0, uint32_t& r1, uint32_t& r2,
                                        uint32_t& r3, uint32_t addr) {
    asm volatile("ldmatrix.sync.aligned.m8n8.x4.shared.b16 {%0,%1,%2,%3}, [%4];"
                 : "=r"(r0), "=r"(r1), "=r"(r2), "=r"(r3) : "r"(addr));
}

__device__ __forceinline__ void cp_async16(uint32_t smem_addr, const void* gptr) {
    asm volatile("cp.async.cg.shared.global [%0], [%1], 16;"
                 :: "r"(smem_addr), "l"(gptr));
}
#define CP_COMMIT() asm volatile("cp.async.commit_group;")
#define CP_WAIT(N)  asm volatile("cp.async.wait_group %0;" :: "n"(N))

#define MBAR_INIT(addr, cnt) \
    asm volatile("mbarrier.init.shared.b64 [%0], %1;" :: "r"(addr), "r"(cnt) : "memory")
#define MBAR_EXPECT_TX(addr, tx) \
    asm volatile("mbarrier.arrive.expect_tx.shared.b64 _, [%0], %1;" \
                 :: "r"(addr), "r"(tx) : "memory")

__device__ __forceinline__ void mbar_wait_parity(uint32_t mbar, uint32_t parity) {
    asm volatile(
        "{\n\t.reg .pred P;\n\t"
        "WL_%=:\n\t"
        "mbarrier.try_wait.parity.acquire.cta.shared::cta.b64 P, [%0], %1, 0x989680;\n\t"
        "@P bra.uni WD_%=;\n\t"
        "bra.uni WL_%=;\n\t"
        "WD_%=:\n\t}"
        :: "r"(mbar), "r"(parity) : "memory");
}

// 1D bulk copy global -> local SMEM, completion via local mbarrier (R10-proven)
__device__ __forceinline__ void bulk_g2s(uint32_t dst, const void* src, uint32_t bytes,
                                         uint32_t mbar) {
    asm volatile(
        "cp.async.bulk.shared::cluster.global.mbarrier::complete_tx::bytes"
        " [%0], [%1], %2, [%3];"
        :: "r"(dst), "l"(src), "r"(bytes), "r"(mbar) : "memory");
}

__device__ __forceinline__ float sigmoid_fast(float x) {
    return __fdividef(1.0f, 1.0f + __expf(-x));
}
__device__ __forceinline__ float tanh_fast(float x) {
    float e = __expf(-2.0f * x);
    return __fdividef(1.0f - e, 1.0f + e);
}

// ---------------- kernel 0: repack weights/bias, convert X, init state ------
__global__ void pack_kernel(const float* __restrict__ X,
                            const float* __restrict__ Wf, const float* __restrict__ Wi,
                            const float* __restrict__ Wg, const float* __restrict__ Wo,
                            const float* __restrict__ bf, const float* __restrict__ bi,
                            const float* __restrict__ bg, const float* __restrict__ bo) {
    int idx = blockIdx.x * blockDim.x + threadIdx.x;   // over 4M
    if (idx < D_SZ * G4) {
        int j = idx >> 10;       // packed col
        int k = idx & 1023;
        int n = j >> 2;
        int g = j & 3;
        const float* W = (g == 0) ? Wf : (g == 1) ? Wi : (g == 2) ? Wg : Wo;
        g_Wxh[idx] = __float2half(W[k * H_SZ + n]);
        g_Whp[idx] = __float2half(W[(D_SZ + k) * H_SZ + n]);
    }
    // X -> fp16: 8M float4 handled 2 per thread
    #pragma unroll
    for (int r = 0; r < 2; r++) {
        size_t i = (size_t)idx + (size_t)r * ((size_t)D_SZ * G4);
        float4 v = ((const float4*)X)[i];
        __half2* dst = (__half2*)g_Xh;
        dst[2 * i]     = __floats2half2_rn(v.x, v.y);
        dst[2 * i + 1] = __floats2half2_rn(v.z, v.w);
    }
    if (idx < G4) {
        int n = idx >> 2, g = idx & 3;
        const float* bb = (g == 0) ? bf : (g == 1) ? bi : (g == 2) ? bg : bo;
        g_b4[idx] = bb[n];
    }
    if (idx < 65536) g_h[0][idx] = __float2half(0.0f);
    if (idx < 128) g_bar2[idx] = 0u;
}

// ---------------- kernel 1: Gx = X @ Wx + b (3-stage cp.async + ldmatrix) ---
#define GX_STAGE_B 32768
#define GX_SMEM    (3 * GX_STAGE_B)

__global__ __launch_bounds__(256, 2) void gemm_x_kernel() {
    extern __shared__ unsigned char dsm[];
    uint32_t sbase = (uint32_t)__cvta_generic_to_shared(dsm);

    int tid  = threadIdx.x;
    int warp = tid >> 5, lane = tid & 31;
    int wm = warp >> 2, wn = warp & 3;
    int grp = lane >> 2, tig = lane & 3;
    int g8  = lane >> 3, lr = lane & 7;
    int bm = blockIdx.y * 128, bn = blockIdx.x * 128;

    int cr[4], cc[4];
    uint32_t soff[4];
    #pragma unroll
    for (int i = 0; i < 4; i++) {
        int l = tid + i * 256;
        cr[i] = l >> 3;
        cc[i] = l & 7;
        soff[i] = (uint32_t)(cr[i] * 128 + ((cc[i] ^ (cr[i] & 7)) * 16));
    }

    auto issue = [&](int stage, int kt) {
        uint32_t st = sbase + stage * GX_STAGE_B;
        #pragma unroll
        for (int i = 0; i < 4; i++) {
            cp_async16(st + soff[i],
                       &g_Xh[(size_t)(bm + cr[i]) * D_SZ + kt * 64 + cc[i] * 8]);
            cp_async16(st + 16384 + soff[i],
                       &g_Wxh[(size_t)(bn + cr[i]) * D_SZ + kt * 64 + cc[i] * 8]);
        }
        CP_COMMIT();
    };

    float acc[4][4][4];
    #pragma unroll
    for (int i = 0; i < 4; i++)
        #pragma unroll
        for (int j = 0; j < 4; j++)
            #pragma unroll
            for (int k = 0; k < 4; k++) acc[i][j][k] = 0.0f;

    issue(0, 0);
    issue(1, 1);

    for (int it = 0; it < 16; it++) {
        if (it < 15) { CP_WAIT(1); } else { CP_WAIT(0); }
        __syncthreads();
        if (it + 2 < 16) issue((it + 2) % 3, it + 2);

        uint32_t st = sbase + (it % 3) * GX_STAGE_B;
        #pragma unroll
        for (int k16 = 0; k16 < 4; k16++) {
            uint32_t A[4][4], Bf[2][4];
            #pragma unroll
            for (int mt = 0; mt < 4; mt++) {
                int m = wm * 64 + mt * 16 + (g8 & 1) * 8 + lr;
                int ch = k16 * 2 + (g8 >> 1);
                ldsm_x4(A[mt][0], A[mt][1], A[mt][2], A[mt][3],
                        st + m * 128 + ((ch ^ (m & 7)) * 16));
            }
            #pragma unroll
            for (int p = 0; p < 2; p++) {
                int n = wn * 32 + p * 16 + (g8 >> 1) * 8 + lr;
                int ch = k16 * 2 + (g8 & 1);
                ldsm_x4(Bf[p][0], Bf[p][1], Bf[p][2], Bf[p][3],
                        st + 16384 + n * 128 + ((ch ^ (n & 7)) * 16));
            }
            #pragma unroll
            for (int mt = 0; mt < 4; mt++)
                #pragma unroll
                for (int p = 0; p < 2; p++) {
                    mma_f16(acc[mt][2 * p],     A[mt], &Bf[p][0]);
                    mma_f16(acc[mt][2 * p + 1], A[mt], &Bf[p][2]);
                }
        }
        __syncthreads();
    }

    __half* sE = (__half*)dsm;     // 128 x 136 halfs
    #pragma unroll
    for (int mt = 0; mt < 4; mt++)
        #pragma unroll
        for (int nt = 0; nt < 4; nt++) {
            int lc = wn * 32 + nt * 8 + 2 * tig;
            int col = bn + lc;
            float b0 = g_b4[col], b1 = g_b4[col + 1];
            int r = wm * 64 + mt * 16 + grp;
            *(__half2*)&sE[r * 136 + lc] =
                __floats2half2_rn(acc[mt][nt][0] + b0, acc[mt][nt][1] + b1);
            *(__half2*)&sE[(r + 8) * 136 + lc] =
                __floats2half2_rn(acc[mt][nt][2] + b0, acc[mt][nt][3] + b1);
        }
    __syncthreads();
    #pragma unroll
    for (int i = 0; i < 8; i++) {
        int l = tid + i * 256;
        int row = l >> 4, c8 = l & 15;
        *(uint4*)&g_Gxh[(size_t)(bm + row) * G4 + bn + c8 * 8] =
            *(const uint4*)&sE[row * 136 + c8 * 8];
    }
}

// ---------------- kernel 2: persistent recurrence ---------------------------
// R15 pipeline (quarter counters + bulk TMA + early arrive), ONE change:
// Wh B-fragments live permanently in REGISTERS (loaded once from g_Whp).
// Hot loop = ldsm + mma only: no LDS, no Wh smem.
#define OFF_HQ   0                     // 4 quarters x 32768 B
#define OFF_GA   131072
#define OFF_GB   139520
#define OFF_MBAR 147968                // 4 mbarriers
#define SMEM_TOTAL_R 148000
#define QBYTES   32768

__global__ __launch_bounds__(256, 1) void lstm_persistent_kernel(
        float* __restrict__ out, int write_tails) {
    extern __shared__ unsigned char smem[];
    float (*sGA)[33] = (float(*)[33])(smem + OFF_GA);
    float (*sGB)[33] = (float(*)[33])(smem + OFF_GB);
    uint32_t sb = (uint32_t)__cvta_generic_to_shared(smem);

    int tid  = threadIdx.x;
    int warp = tid >> 5, lane = tid & 31;
    int wk = warp >> 1, wm = warp & 1;     // 4 k-split x 2 m-split
    int grp = lane >> 2, tig = lane & 3;
    int g8 = lane >> 3, lr = lane & 7;
    int blk = blockIdx.x;

    if (tid == 0) {
        #pragma unroll
        for (int q = 0; q < 4; q++) MBAR_INIT(sb + OFF_MBAR + q * 8, 1);
    }

    // ---- one-time: this warp's Wh B-fragments -> registers (128 regs) ----
    // B frag (part, kk, nt): b0 = Wh[col][kg..kg+1], b1 = Wh[col][kg+8..kg+9]
    // with col = blk*32 + nt*8 + grp, kg = (q*16 + lk)*16 + 2*tig,
    // q = part*2 + (wk>>1), lk = (wk&1)*8 + kk.
    uint32_t Breg[2][8][4][2];
    {
        const __half* wb = g_Whp + (size_t)blk * 32768;
        #pragma unroll
        for (int part = 0; part < 2; part++) {
            int q = part * 2 + (wk >> 1);
            #pragma unroll
            for (int kk = 0; kk < 8; kk++) {
                int lk = (wk & 1) * 8 + kk;
                int kg = (q * 16 + lk) * 16 + 2 * tig;
                #pragma unroll
                for (int nt = 0; nt < 4; nt++) {
                    const __half* p = wb + (size_t)(nt * 8 + grp) * 1024 + kg;
                    Breg[part][kk][nt][0] = *(const uint32_t*)p;
                    Breg[part][kk][nt][1] = *(const uint32_t*)(p + 8);
                }
            }
        }
    }
    __syncthreads();

    // per-lane ldmatrix A row (constant across steps)
    int rowA = wm * 32 + (g8 & 1) * 8 + lr;

    // per-thread pointwise coordinates
    int pr = (tid * 2) >> 3;          // batch row 0..63
    int pc = (tid * 2) & 7;           // local h-col (even)
    int pn = blk * 8 + pc;            // global h-col (even)
    int qp   = pn >> 8;               // producer k-quarter
    int hch  = (pn & 255) >> 3;       // 16 B chunk within 512 B row
    int qcnt = (blk >> 5) * 32;       // counter slot for this CTA's quarter

    float creg[2] = {0.0f, 0.0f};

    // Gx prefetch for t=0
    uint2 gxr[2];
    #pragma unroll
    for (int p = 0; p < 2; p++) {
        gxr[p] = __ldcg((const uint2*)&g_Gxh[(size_t)pr * G4 + blk * 32 +
                                             (pc + p) * 4]);
    }

    // step-0 h loads (initial h ready; no barrier needed)
    if (tid == 0) {
        const char* hbg = (const char*)g_h;
        #pragma unroll
        for (int q = 0; q < 4; q++) {
            uint32_t mb = sb + OFF_MBAR + q * 8;
            MBAR_EXPECT_TX(mb, QBYTES);
            bulk_g2s(sb + OFF_HQ + q * QBYTES, hbg + q * QBYTES, QBYTES, mb);
        }
    }

    for (int t = 0; t < T_STEPS; t++) {
        float acc[2][4][4];
        #pragma unroll
        for (int i = 0; i < 2; i++)
            #pragma unroll
            for (int j = 0; j < 4; j++)
                #pragma unroll
                for (int k = 0; k < 4; k++) acc[i][j][k] = 0.0f;

        #pragma unroll
        for (int part = 0; part < 2; part++) {
            int q = part * 2 + (wk >> 1);
            mbar_wait_parity(sb + OFF_MBAR + q * 8, (uint32_t)(t & 1));
            uint32_t qb = sb + OFF_HQ + q * QBYTES;
            #pragma unroll
            for (int kk = 0; kk < 8; kk++) {
                int lk = (wk & 1) * 8 + kk;       // local k16 in quarter
                int c  = lk * 2 + (g8 >> 1);      // chunk 0..31
                uint32_t A0[4], A1[4];
                {
                    int row = rowA;
                    uint32_t a = qb + row * 512 +
                                 (uint32_t)((((c & 7) ^ (row & 7)) | (c & ~7)) * 16);
                    ldsm_x4(A0[0], A0[1], A0[2], A0[3], a);
                    row = rowA + 16;
                    a = qb + row * 512 +
                        (uint32_t)((((c & 7) ^ (row & 7)) | (c & ~7)) * 16);
                    ldsm_x4(A1[0], A1[1], A1[2], A1[3], a);
                }
                #pragma unroll
                for (int nt = 0; nt < 4; nt++) {
                    mma_f16(acc[0][nt], A0, Breg[part][kk][nt]);
                    mma_f16(acc[1][nt], A1, Breg[part][kk][nt]);
                }
            }
        }

        // 2-round k-split reduction
        if ((wk & 1) == 0) {
            float (*d)[33] = (wk == 0) ? sGA : sGB;
            #pragma unroll
            for (int mt = 0; mt < 2; mt++)
                #pragma unroll
                for (int nt = 0; nt < 4; nt++) {
                    int r = wm * 32 + mt * 16 + grp, c = nt * 8 + 2 * tig;
                    d[r    ][c]     = acc[mt][nt][0];
                    d[r    ][c + 1] = acc[mt][nt][1];
                    d[r + 8][c]     = acc[mt][nt][2];
                    d[r + 8][c + 1] = acc[mt][nt][3];
                }
        }
        __syncthreads();
        if ((wk & 1) == 1) {
            float (*d)[33] = (wk == 1) ? sGA : sGB;
            #pragma unroll
            for (int mt = 0; mt < 2; mt++)
                #pragma unroll
                for (int nt = 0; nt < 4; nt++) {
                    int r = wm * 32 + mt * 16 + grp, c = nt * 8 + 2 * tig;
                    d[r    ][c]     += acc[mt][nt][0];
                    d[r    ][c + 1] += acc[mt][nt][1];
                    d[r + 8][c]     += acc[mt][nt][2];
                    d[r + 8][c + 1] += acc[mt][nt][3];
                }
        }
        __syncthreads();

        // fused pointwise: compute, store ONLY h, fence, early arrive
        float hn2[2], cn2[2];
        #pragma unroll
        for (int p = 0; p < 2; p++) {
            int c = pc + p;
            float2 g01 = __half22float2(*(__half2*)&gxr[p].x);
            float2 g23 = __half22float2(*(__half2*)&gxr[p].y);
            float pf = sGA[pr][c * 4 + 0] + sGB[pr][c * 4 + 0] + g01.x;
            float pi = sGA[pr][c * 4 + 1] + sGB[pr][c * 4 + 1] + g01.y;
            float pg = sGA[pr][c * 4 + 2] + sGB[pr][c * 4 + 2] + g23.x;
            float po = sGA[pr][c * 4 + 3] + sGB[pr][c * 4 + 3] + g23.y;
            float f = sigmoid_fast(pf);
            float i = sigmoid_fast(pi);
            float g = tanh_fast(pg);
            float o = sigmoid_fast(po);
            float cn = f * creg[p] + i * g;
            creg[p] = cn;
            cn2[p] = cn;
            hn2[p] = o * tanh_fast(cn);
        }
        // packed h store into the swizzled quarter image
        {
            char* hout = (char*)g_h + (size_t)((t + 1) & 1) * 131072 +
                         (size_t)qp * QBYTES;
            uint32_t off = (uint32_t)pr * 512 +
                           (uint32_t)((((hch & 7) ^ (pr & 7)) | (hch & ~7)) * 16) +
                           (uint32_t)(pn & 7) * 2;
            *(__half2*)(hout + off) = __floats2half2_rn(hn2[0], hn2[1]);
        }
        __threadfence();
        __syncthreads();
        // EARLY arrival on this CTA's quarter counter
        if (t < T_STEPS - 1 && tid == 0)
            atomicAdd(&g_bar2[qcnt], 1u);

        // out[] stores + tails + Gx(t+1) prefetch overlap the barrier wait
        *(float2*)&out[(size_t)(t * B_SZ + pr) * H_SZ + pn] =
            make_float2(hn2[0], hn2[1]);
        if (t == T_STEPS - 1 && write_tails) {
            int ci = pr * H_SZ + pn;
            *(float2*)&out[(size_t)T_STEPS * B_SZ * H_SZ + ci] =
                make_float2(hn2[0], hn2[1]);
            *(float2*)&out[(size_t)T_STEPS * B_SZ * H_SZ + B_SZ * H_SZ + ci] =
                make_float2(cn2[0], cn2[1]);
        }
        {
            int tn = (t + 1 < T_STEPS) ? t + 1 : t;
            #pragma unroll
            for (int p = 0; p < 2; p++) {
                gxr[p] = __ldcg((const uint2*)&g_Gxh[(size_t)(tn * B_SZ + pr) * G4 +
                                                     blk * 32 + (pc + p) * 4]);
            }
        }

        // tid0: per-quarter poll -> issue 32 KB TMA; no release syncthreads.
        if (t < T_STEPS - 1 && tid == 0) {
            unsigned target = (unsigned)(t + 1) * 32u;
            const char* hbg = (const char*)g_h + (size_t)((t + 1) & 1) * 131072;
            #pragma unroll
            for (int q = 0; q < 4; q++) {
                while (*((volatile unsigned*)&g_bar2[q * 32]) < target) {
                    __nanosleep(20);
                }
                uint32_t mb = sb + OFF_MBAR + q * 8;
                MBAR_EXPECT_TX(mb, QBYTES);
                bulk_g2s(sb + OFF_HQ + q * QBYTES, hbg + q * QBYTES, QBYTES, mb);
            }
        }
    }
}

// ---------------- launch ----------------
extern "C" void kernel_launch(void* const* d_in, const int* in_sizes, int n_in,
                              void* d_out, int out_size) {
    const float* x  = (const float*)d_in[0];
    const float* Wf = (const float*)d_in[1];
    const float* bf = (const float*)d_in[2];
    const float* Wi = (const float*)d_in[3];
    const float* bi = (const float*)d_in[4];
    const float* Wg = (const float*)d_in[5];
    const float* bg = (const float*)d_in[6];
    const float* Wo = (const float*)d_in[7];
    const float* bo = (const float*)d_in[8];
    float* out = (float*)d_out;

    int write_tails =
        (out_size >= T_STEPS * B_SZ * H_SZ + 2 * B_SZ * H_SZ) ? 1 : 0;

    static int smem_set = 0;
    if (!smem_set) {
        cudaFuncSetAttribute(lstm_persistent_kernel,
                             cudaFuncAttributeMaxDynamicSharedMemorySize,
                             SMEM_TOTAL_R);
        cudaFuncSetAttribute(gemm_x_kernel,
                             cudaFuncAttributeMaxDynamicSharedMemorySize,
                             GX_SMEM);
        smem_set = 1;
    }

    pack_kernel<<<(D_SZ * G4 + 255) / 256, 256>>>(x, Wf, Wi, Wg, Wo,
                                                  bf, bi, bg, bo);

    dim3 g1(G4 / 128, M_TOT / 128);
    gemm_x_kernel<<<g1, 256, GX_SMEM>>>();

    lstm_persistent_kernel<<<NBLK, 256, SMEM_TOTAL_R>>>(out, write_tails);
}